// round 2
// baseline (speedup 1.0000x reference)
#include <cuda_runtime.h>
#include <cuda_bf16.h>
#include <cstdint>

// Problem dims
#define M_TOT 8192      // 16 * 512
#define N_TOT 4096      // OUT_F
#define K_TOT 1024      // IN_F

// ---------------- scratch (device globals; no allocation allowed) ----------
__device__ __nv_bfloat16 g_xh[(size_t)M_TOT * K_TOT];
__device__ __nv_bfloat16 g_xl[(size_t)M_TOT * K_TOT];
__device__ __nv_bfloat16 g_Wh[(size_t)N_TOT * K_TOT];
__device__ __nv_bfloat16 g_Wl[(size_t)N_TOT * K_TOT];

// ---------------- small PTX helpers ----------------------------------------
__device__ __forceinline__ unsigned smem_u32(const void* p) {
    return (unsigned)__cvta_generic_to_shared(p);
}
__device__ __forceinline__ void cp_async16(unsigned smem, const void* gptr) {
    asm volatile("cp.async.cg.shared.global [%0], [%1], 16;\n"
                 :: "r"(smem), "l"(gptr));
}
__device__ __forceinline__ void cp_commit() {
    asm volatile("cp.async.commit_group;\n" ::: "memory");
}
__device__ __forceinline__ void cp_wait_all() {
    asm volatile("cp.async.wait_group 0;\n" ::: "memory");
}
__device__ __forceinline__ void ldsm_x4(unsigned& r0, unsigned& r1,
                                        unsigned& r2, unsigned& r3,
                                        unsigned addr) {
    asm volatile("ldmatrix.sync.aligned.m8n8.x4.shared.b16 {%0,%1,%2,%3}, [%4];\n"
                 : "=r"(r0), "=r"(r1), "=r"(r2), "=r"(r3) : "r"(addr));
}
__device__ __forceinline__ void mma_bf16(float* d, const unsigned* a,
                                         const unsigned* b, const float* c) {
    asm volatile(
        "mma.sync.aligned.m16n8k16.row.col.f32.bf16.bf16.f32 "
        "{%0,%1,%2,%3}, {%4,%5,%6,%7}, {%8,%9}, {%10,%11,%12,%13};\n"
        : "=f"(d[0]), "=f"(d[1]), "=f"(d[2]), "=f"(d[3])
        : "r"(a[0]), "r"(a[1]), "r"(a[2]), "r"(a[3]),
          "r"(b[0]), "r"(b[1]),
          "f"(c[0]), "f"(c[1]), "f"(c[2]), "f"(c[3]));
}

// ---------------- Kernel 1: build W_mix and split into bf16 hi/lo ----------
// W_mix[o,i] = a0*W[o,i] + sum_{bs in {2,4,8,16}} (a_bs / bs) * diag_sum
// where within each bs x bs block, diag_sum for output (r,c) is
//   sum_k W_block[k][(k + (r-c)) mod bs]   (wrap diagonal with col-row == r-c)
__global__ void mix_weight_kernel(const float* __restrict__ W,
                                  const float* __restrict__ alphas) {
    __shared__ float tile[16][17];
    const int tr = threadIdx.y, tc = threadIdx.x;
    const int br = blockIdx.y * 16, bc = blockIdx.x * 16;

    tile[tr][tc] = W[(size_t)(br + tr) * K_TOT + bc + tc];

    // softmax over 5 alphas (computed redundantly per thread; tiny)
    float a[5];
#pragma unroll
    for (int i = 0; i < 5; i++) a[i] = __ldg(alphas + i);
    float mx = a[0];
#pragma unroll
    for (int i = 1; i < 5; i++) mx = fmaxf(mx, a[i]);
    float e[5], s = 0.f;
#pragma unroll
    for (int i = 0; i < 5; i++) { e[i] = expf(a[i] - mx); s += e[i]; }
    const float inv = 1.0f / s;

    __syncthreads();

    float val = e[0] * inv * tile[tr][tc];
#pragma unroll
    for (int bsi = 0; bsi < 4; bsi++) {
        const int bs = 2 << bsi;                // 2,4,8,16
        const int rb = tr & ~(bs - 1);
        const int cb = tc & ~(bs - 1);
        const int d  = (tr - tc) & (bs - 1);
        float sum = 0.f;
        for (int k = 0; k < bs; k++)
            sum += tile[rb + k][cb + ((k + d) & (bs - 1))];
        val += (e[bsi + 1] * inv / (float)bs) * sum;
    }

    const size_t idx = (size_t)(br + tr) * K_TOT + bc + tc;
    __nv_bfloat16 h = __float2bfloat16(val);
    g_Wh[idx] = h;
    g_Wl[idx] = __float2bfloat16(val - __bfloat162float(h));
}

// ---------------- Kernel 2: split x into bf16 hi/lo (vectorized) -----------
__global__ void split_x_kernel(const float* __restrict__ x) {
    const int i = blockIdx.x * blockDim.x + threadIdx.x;   // float4 index
    const float4 v = reinterpret_cast<const float4*>(x)[i];
    __nv_bfloat16 hx = __float2bfloat16(v.x);
    __nv_bfloat16 hy = __float2bfloat16(v.y);
    __nv_bfloat16 hz = __float2bfloat16(v.z);
    __nv_bfloat16 hw = __float2bfloat16(v.w);
    __nv_bfloat162* ph = reinterpret_cast<__nv_bfloat162*>(g_xh) + i * 2;
    __nv_bfloat162* pl = reinterpret_cast<__nv_bfloat162*>(g_xl) + i * 2;
    ph[0] = __nv_bfloat162(hx, hy);
    ph[1] = __nv_bfloat162(hz, hw);
    pl[0] = __nv_bfloat162(__float2bfloat16(v.x - __bfloat162float(hx)),
                           __float2bfloat16(v.y - __bfloat162float(hy)));
    pl[1] = __nv_bfloat162(__float2bfloat16(v.z - __bfloat162float(hz)),
                           __float2bfloat16(v.w - __bfloat162float(hw)));
}

// ---------------- Kernel 3: GEMM  out = A @ B^T + bias ---------------------
// Logical K' = 3072: segment 0 = xh*Wh, segment 1 = xh*Wl, segment 2 = xl*Wh.
// CTA tile 128x128, BK=32, 8 warps (2x4), warp tile 64x32, double-buffered
// cp.async, padded smem stride 40 bf16 (80B) -> conflict-free ldmatrix.
#define BM 128
#define BN 128
#define BK 32
#define LDA 40
#define NTILES 96   // 3 segments * (1024/32)

__global__ __launch_bounds__(256, 2)
void gemm_kernel(const float* __restrict__ bias, float* __restrict__ out) {
    __shared__ __nv_bfloat16 sA[2][BM * LDA];
    __shared__ __nv_bfloat16 sB[2][BN * LDA];

    const int tid  = threadIdx.x;
    const int warp = tid >> 5;
    const int lane = tid & 31;
    const int warpM = warp >> 2;   // 0..1
    const int warpN = warp & 3;    // 0..3
    const int cM = blockIdx.y * BM;
    const int cN = blockIdx.x * BN;

    float acc[4][4][4];
#pragma unroll
    for (int mi = 0; mi < 4; mi++)
#pragma unroll
        for (int ni = 0; ni < 4; ni++)
#pragma unroll
            for (int r = 0; r < 4; r++) acc[mi][ni][r] = 0.f;

    auto issue_tile = [&](int kt, int buf) {
        const int seg = kt >> 5;
        const int k0  = (kt & 31) * BK;
        const __nv_bfloat16* Ap = (seg == 2) ? g_xl : g_xh;
        const __nv_bfloat16* Bp = (seg == 1) ? g_Wl : g_Wh;
#pragma unroll
        for (int j = 0; j < 2; j++) {
            const int id  = tid + j * 256;
            const int row = id >> 2;
            const int cc  = id & 3;
            cp_async16(smem_u32(&sA[buf][row * LDA + cc * 8]),
                       Ap + (size_t)(cM + row) * K_TOT + k0 + cc * 8);
            cp_async16(smem_u32(&sB[buf][row * LDA + cc * 8]),
                       Bp + (size_t)(cN + row) * K_TOT + k0 + cc * 8);
        }
        cp_commit();
    };

    issue_tile(0, 0);

    for (int kt = 0; kt < NTILES; kt++) {
        const int buf = kt & 1;
        cp_wait_all();
        __syncthreads();                 // tile ready; prev compute done
        if (kt + 1 < NTILES) issue_tile(kt + 1, buf ^ 1);

#pragma unroll
        for (int ks = 0; ks < 2; ks++) {
            const int k0 = ks * 16;
            unsigned af[4][4];
#pragma unroll
            for (int mi = 0; mi < 4; mi++) {
                const int row = warpM * 64 + mi * 16 + (lane & 15);
                const int col = k0 + (lane >> 4) * 8;
                ldsm_x4(af[mi][0], af[mi][1], af[mi][2], af[mi][3],
                        smem_u32(&sA[buf][row * LDA + col]));
            }
            unsigned bfr[4][2];
#pragma unroll
            for (int nj = 0; nj < 2; nj++) {
                const int row = warpN * 32 + nj * 16 + (lane & 15);
                const int col = k0 + (lane >> 4) * 8;
                unsigned r0, r1, r2, r3;
                ldsm_x4(r0, r1, r2, r3, smem_u32(&sB[buf][row * LDA + col]));
                bfr[nj * 2 + 0][0] = r0; bfr[nj * 2 + 0][1] = r2;
                bfr[nj * 2 + 1][0] = r1; bfr[nj * 2 + 1][1] = r3;
            }
#pragma unroll
            for (int mi = 0; mi < 4; mi++)
#pragma unroll
                for (int ni = 0; ni < 4; ni++)
                    mma_bf16(acc[mi][ni], af[mi], bfr[ni], acc[mi][ni]);
        }
    }

    // epilogue: out[m][n] = acc + bias[n]
#pragma unroll
    for (int mi = 0; mi < 4; mi++) {
#pragma unroll
        for (int ni = 0; ni < 4; ni++) {
            const int r0 = cM + warpM * 64 + mi * 16 + (lane >> 2);
            const int c0 = cN + warpN * 32 + ni * 8 + (lane & 3) * 2;
            const float2 bb = *reinterpret_cast<const float2*>(bias + c0);
            float2 v0, v1;
            v0.x = acc[mi][ni][0] + bb.x;
            v0.y = acc[mi][ni][1] + bb.y;
            v1.x = acc[mi][ni][2] + bb.x;
            v1.y = acc[mi][ni][3] + bb.y;
            *reinterpret_cast<float2*>(out + (size_t)r0 * N_TOT + c0)       = v0;
            *reinterpret_cast<float2*>(out + (size_t)(r0 + 8) * N_TOT + c0) = v1;
        }
    }
}

// ---------------- launch ----------------------------------------------------
extern "C" void kernel_launch(void* const* d_in, const int* in_sizes, int n_in,
                              void* d_out, int out_size) {
    const float* x      = (const float*)d_in[0];   // [16,512,1024]
    const float* weight = (const float*)d_in[1];   // [4096,1024]
    const float* alphas = (const float*)d_in[2];   // [5]
    const float* bias   = (const float*)d_in[3];   // [4096]
    float* out = (float*)d_out;                    // [16,512,4096]

    mix_weight_kernel<<<dim3(K_TOT / 16, N_TOT / 16), dim3(16, 16)>>>(weight, alphas);

    const int n4 = (M_TOT * K_TOT) / 4;            // float4 elements
    split_x_kernel<<<n4 / 256, 256>>>(x);

    gemm_kernel<<<dim3(N_TOT / BN, M_TOT / BM), 256>>>(bias, out);
}

// round 5
// speedup vs baseline: 2.7096x; 2.7096x over previous
#include <cuda_runtime.h>
#include <cuda_fp16.h>
#include <cstdint>

#define M_TOT 8192      // 16 * 512
#define N_TOT 4096      // OUT_F
#define K_TOT 1024      // IN_F

// ---------------- scratch (device globals; no allocation allowed) ----------
__device__ __half g_xm[(size_t)M_TOT * K_TOT];
__device__ __half g_Wm[(size_t)N_TOT * K_TOT];

// ---------------- PTX helpers ----------------------------------------------
__device__ __forceinline__ unsigned smem_u32(const void* p) {
    return (unsigned)__cvta_generic_to_shared(p);
}
__device__ __forceinline__ void cp_async16(unsigned smem, const void* gptr) {
    asm volatile("cp.async.cg.shared.global [%0], [%1], 16;\n"
                 :: "r"(smem), "l"(gptr));
}
__device__ __forceinline__ void cp_commit() {
    asm volatile("cp.async.commit_group;\n" ::: "memory");
}
__device__ __forceinline__ void cp_wait_all() {
    asm volatile("cp.async.wait_group 0;\n" ::: "memory");
}
__device__ __forceinline__ void ldsm_x4(unsigned& r0, unsigned& r1,
                                        unsigned& r2, unsigned& r3,
                                        unsigned addr) {
    asm volatile("ldmatrix.sync.aligned.m8n8.x4.shared.b16 {%0,%1,%2,%3}, [%4];\n"
                 : "=r"(r0), "=r"(r1), "=r"(r2), "=r"(r3) : "r"(addr));
}
__device__ __forceinline__ void mma_fp16(float* d, const unsigned* a,
                                         const unsigned* b, const float* c) {
    asm volatile(
        "mma.sync.aligned.m16n8k16.row.col.f32.f16.f16.f32 "
        "{%0,%1,%2,%3}, {%4,%5,%6,%7}, {%8,%9}, {%10,%11,%12,%13};\n"
        : "=f"(d[0]), "=f"(d[1]), "=f"(d[2]), "=f"(d[3])
        : "r"(a[0]), "r"(a[1]), "r"(a[2]), "r"(a[3]),
          "r"(b[0]), "r"(b[1]),
          "f"(c[0]), "f"(c[1]), "f"(c[2]), "f"(c[3]));
}

// ---------------- Kernel 1 (fused prep): mix W + convert x ------------------
// blocks [0, 16384): one 16x16 W superblock each -> g_Wm (fp16)
// blocks [16384, 24576): x convert (float4 granularity) -> g_xm (fp16)
__global__ __launch_bounds__(256)
void prep_kernel(const float* __restrict__ x,
                 const float* __restrict__ W,
                 const float* __restrict__ alphas) {
    const int b = blockIdx.x;
    const int tid = threadIdx.x;
    if (b < 16384) {
        __shared__ float tile[16][17];
        __shared__ float coef[5];
        const int tr = tid >> 4, tc = tid & 15;
        const int br = (b >> 6) * 16, bc = (b & 63) * 16;   // K/16 = 64 blocks/row

        if (tid == 0) {
            float a[5], mx;
            #pragma unroll
            for (int i = 0; i < 5; i++) a[i] = __ldg(alphas + i);
            mx = a[0];
            #pragma unroll
            for (int i = 1; i < 5; i++) mx = fmaxf(mx, a[i]);
            float e[5], s = 0.f;
            #pragma unroll
            for (int i = 0; i < 5; i++) { e[i] = expf(a[i] - mx); s += e[i]; }
            const float inv = 1.0f / s;
            coef[0] = e[0] * inv;
            #pragma unroll
            for (int i = 1; i < 5; i++)
                coef[i] = e[i] * inv / (float)(1 << i);    // /bs folded in
        }
        tile[tr][tc] = W[(size_t)(br + tr) * K_TOT + bc + tc];
        __syncthreads();

        float val = coef[0] * tile[tr][tc];
        #pragma unroll
        for (int bsi = 0; bsi < 4; bsi++) {
            const int bs = 2 << bsi;                       // 2,4,8,16
            const int rb = tr & ~(bs - 1);
            const int cb = tc & ~(bs - 1);
            const int d  = (tr - tc) & (bs - 1);
            float sum = 0.f;
            for (int k = 0; k < bs; k++)
                sum += tile[rb + k][cb + ((k + d) & (bs - 1))];
            val += coef[bsi + 1] * sum;
        }
        g_Wm[(size_t)(br + tr) * K_TOT + bc + tc] = __float2half(val);
    } else {
        const int i = (b - 16384) * 256 + tid;             // float4 index
        const float4 v = reinterpret_cast<const float4*>(x)[i];
        __half2* ph = reinterpret_cast<__half2*>(g_xm) + i * 2;
        ph[0] = __half2(__float2half(v.x), __float2half(v.y));
        ph[1] = __half2(__float2half(v.z), __float2half(v.w));
    }
}

// ---------------- Kernel 2: GEMM  out = x @ Wm^T + bias  (fp16 mma.sync) ----
// CTA tile 128x128, BK=32, 8 warps (2x4), warp tile 64x32, double-buffered
// cp.async, padded smem stride 40 halves (80B) -> conflict-free ldmatrix.
#define BM 128
#define BN 128
#define BK 32
#define LDA 40
#define NTILES 32   // 1024 / 32

__global__ __launch_bounds__(256, 2)
void gemm_kernel(const float* __restrict__ bias, float* __restrict__ out) {
    __shared__ __half sA[2][BM * LDA];
    __shared__ __half sB[2][BN * LDA];

    const int tid  = threadIdx.x;
    const int warp = tid >> 5;
    const int lane = tid & 31;
    const int warpM = warp >> 2;   // 0..1
    const int warpN = warp & 3;    // 0..3
    const int cM = blockIdx.y * BM;
    const int cN = blockIdx.x * BN;

    float acc[4][4][4];
#pragma unroll
    for (int mi = 0; mi < 4; mi++)
#pragma unroll
        for (int ni = 0; ni < 4; ni++)
#pragma unroll
            for (int r = 0; r < 4; r++) acc[mi][ni][r] = 0.f;

    auto issue_tile = [&](int kt, int buf) {
        const int k0 = kt * BK;
#pragma unroll
        for (int j = 0; j < 2; j++) {
            const int id  = tid + j * 256;
            const int row = id >> 2;
            const int cc  = id & 3;
            cp_async16(smem_u32(&sA[buf][row * LDA + cc * 8]),
                       g_xm + (size_t)(cM + row) * K_TOT + k0 + cc * 8);
            cp_async16(smem_u32(&sB[buf][row * LDA + cc * 8]),
                       g_Wm + (size_t)(cN + row) * K_TOT + k0 + cc * 8);
        }
        cp_commit();
    };

    issue_tile(0, 0);

    for (int kt = 0; kt < NTILES; kt++) {
        const int buf = kt & 1;
        cp_wait_all();
        __syncthreads();                 // tile ready; prev compute done
        if (kt + 1 < NTILES) issue_tile(kt + 1, buf ^ 1);

#pragma unroll
        for (int ks = 0; ks < 2; ks++) {
            const int k0 = ks * 16;
            unsigned af[4][4];
#pragma unroll
            for (int mi = 0; mi < 4; mi++) {
                const int row = warpM * 64 + mi * 16 + (lane & 15);
                const int col = k0 + (lane >> 4) * 8;
                ldsm_x4(af[mi][0], af[mi][1], af[mi][2], af[mi][3],
                        smem_u32(&sA[buf][row * LDA + col]));
            }
            unsigned bfr[4][2];
#pragma unroll
            for (int nj = 0; nj < 2; nj++) {
                const int row = warpN * 32 + nj * 16 + (lane & 15);
                const int col = k0 + (lane >> 4) * 8;
                unsigned r0, r1, r2, r3;
                ldsm_x4(r0, r1, r2, r3, smem_u32(&sB[buf][row * LDA + col]));
                bfr[nj * 2 + 0][0] = r0; bfr[nj * 2 + 0][1] = r2;
                bfr[nj * 2 + 1][0] = r1; bfr[nj * 2 + 1][1] = r3;
            }
#pragma unroll
            for (int mi = 0; mi < 4; mi++)
#pragma unroll
                for (int ni = 0; ni < 4; ni++)
                    mma_fp16(acc[mi][ni], af[mi], bfr[ni], acc[mi][ni]);
        }
    }

    // epilogue: out[m][n] = acc + bias[n]
#pragma unroll
    for (int mi = 0; mi < 4; mi++) {
#pragma unroll
        for (int ni = 0; ni < 4; ni++) {
            const int r0 = cM + warpM * 64 + mi * 16 + (lane >> 2);
            const int c0 = cN + warpN * 32 + ni * 8 + (lane & 3) * 2;
            const float2 bb = *reinterpret_cast<const float2*>(bias + c0);
            float2 v0, v1;
            v0.x = acc[mi][ni][0] + bb.x;
            v0.y = acc[mi][ni][1] + bb.y;
            v1.x = acc[mi][ni][2] + bb.x;
            v1.y = acc[mi][ni][3] + bb.y;
            *reinterpret_cast<float2*>(out + (size_t)r0 * N_TOT + c0)       = v0;
            *reinterpret_cast<float2*>(out + (size_t)(r0 + 8) * N_TOT + c0) = v1;
        }
    }
}

// ---------------- launch ----------------------------------------------------
extern "C" void kernel_launch(void* const* d_in, const int* in_sizes, int n_in,
                              void* d_out, int out_size) {
    const float* x      = (const float*)d_in[0];   // [16,512,1024]
    const float* weight = (const float*)d_in[1];   // [4096,1024]
    const float* alphas = (const float*)d_in[2];   // [5]
    const float* bias   = (const float*)d_in[3];   // [4096]
    float* out = (float*)d_out;                    // [16,512,4096]

    prep_kernel<<<16384 + 8192, 256>>>(x, weight, alphas);

    gemm_kernel<<<dim3(N_TOT / BN, M_TOT / BM), 256>>>(bias, out);
}